// round 16
// baseline (speedup 1.0000x reference)
#include <cuda_runtime.h>
#include <cuda_bf16.h>
#include <cstdint>

// Problem constants
#define VOCABN 50257
#define SMALLN 512
#define LARGEN 1024
#define NTOK   8192      // B*S = 4*2048

// bf16 staging buffers (device globals: allocation-free scratch)
__device__ __nv_bfloat16 g_Abf[NTOK * SMALLN];    // gathered weight rows, bf16
__device__ __nv_bfloat16 g_Bbf[SMALLN * SMALLN];  // cw, bf16

// ---------------------------------------------------------------------------
// Kernel 1 (merged prep, 2 units/thread for doubled memory-level parallelism):
//   gather units: out[t,0:512] = weight[id]+residual[id,0:512]; stage Abf
//   cw units:     Bbf = bf16(cw)
// ---------------------------------------------------------------------------
#define GATHER_UNITS (NTOK * 128)                 // 1,048,576
#define CW_UNITS     (SMALLN * SMALLN / 4)        // 65,536
#define TOTAL_UNITS  (GATHER_UNITS + CW_UNITS)    // 1,114,112
#define PREP_THREADS (TOTAL_UNITS / 2)            // 557,056

__global__ void prep_kernel(const int* __restrict__ ids,
                            const float4* __restrict__ w4,
                            const float4* __restrict__ r4,
                            const float4* __restrict__ cw4,
                            float4* __restrict__ out4) {
    int t0 = blockIdx.x * blockDim.x + threadIdx.x;
    #pragma unroll
    for (int k = 0; k < 2; k++) {
        int gid = t0 + k * PREP_THREADS;
        if (gid < GATHER_UNITS) {
            int t = gid >> 7;
            int c = gid & 127;
            int id = ids[t];
            float4 a = w4[(size_t)id * 128 + c];
            float4 b = r4[(size_t)id * 256 + c];
            float4 o;
            o.x = a.x + b.x; o.y = a.y + b.y; o.z = a.z + b.z; o.w = a.w + b.w;
            out4[(size_t)t * 256 + c] = o;

            __nv_bfloat162 p0 = {__float2bfloat16(a.x), __float2bfloat16(a.y)};
            __nv_bfloat162 p1 = {__float2bfloat16(a.z), __float2bfloat16(a.w)};
            __nv_bfloat162* ap = reinterpret_cast<__nv_bfloat162*>(
                g_Abf + (size_t)t * SMALLN + c * 4);
            ap[0] = p0;
            ap[1] = p1;
        } else {
            int i = gid - GATHER_UNITS;
            float4 v = cw4[i];
            __nv_bfloat162 p0 = {__float2bfloat16(v.x), __float2bfloat16(v.y)};
            __nv_bfloat162 p1 = {__float2bfloat16(v.z), __float2bfloat16(v.w)};
            __nv_bfloat162* bp =
                reinterpret_cast<__nv_bfloat162*>(g_Bbf + (size_t)i * 4);
            bp[0] = p0;
            bp[1] = p1;
        }
    }
}

// ---------------------------------------------------------------------------
// Kernel 2: EXACT R9 GEMM mainloop (best measured: 24.48us), with one
// prologue addition: L2-prefetch of the epilogue's gathered residual lines
// (2048 x 128B per CTA), issued once, outside the mainloop.
// BM=128, BN=256, BK=64, 256 threads (8 warps 2x4), warp tile 64x64.
// Grid (2, 64) = 128 CTAs = one wave.
// ---------------------------------------------------------------------------
#define BM 128
#define BN 256
#define BK 64
#define KP 72
#define STAGES 3
#define ASZ (BM * KP)
#define BSZ (BN * KP)
#define STAGE_ELEMS (ASZ + BSZ)
#define SMEM_BYTES (STAGES * STAGE_ELEMS * 2)   // 165,888 B

__device__ __forceinline__ void cpa16(void* sm, const void* g) {
    uint32_t s = (uint32_t)__cvta_generic_to_shared(sm);
    asm volatile("cp.async.cg.shared.global [%0], [%1], 16;\n" :: "r"(s), "l"(g));
}
__device__ __forceinline__ void ldsm_x4(uint32_t& d0, uint32_t& d1,
                                        uint32_t& d2, uint32_t& d3, uint32_t a) {
    asm volatile("ldmatrix.sync.aligned.m8n8.x4.shared.b16 {%0,%1,%2,%3}, [%4];"
                 : "=r"(d0), "=r"(d1), "=r"(d2), "=r"(d3) : "r"(a));
}
__device__ __forceinline__ void prefetchL2(const void* p) {
    asm volatile("prefetch.global.L2 [%0];" :: "l"(p));
}

__global__ __launch_bounds__(256, 1)
void gemm_second_half(const int* __restrict__ ids,
                      const float* __restrict__ residual,   // [VOCAB][1024]
                      float* __restrict__ out) {            // [NTOK][1024]
    extern __shared__ __nv_bfloat16 smem[];
    __shared__ int sids[BM];

    const int bn = blockIdx.x;        // 0..1
    const int bm = blockIdx.y;        // 0..63
    const int tid  = threadIdx.x;
    const int warp = tid >> 5;
    const int lane = tid & 31;
    const int wm = warp >> 2;         // 0..1  (64-row slab)
    const int wn = warp & 3;          // 0..3  (64-col slab)
    const int g  = lane >> 2;         // 0..7
    const int tg = lane & 3;          // 0..3

    if (tid < BM) sids[tid] = ids[bm * BM + tid];

    const uint32_t smem_b = (uint32_t)__cvta_generic_to_shared(smem);
    const uint32_t a_off = (uint32_t)(((lane & 15) * KP + ((lane >> 4) << 3)) * 2);
    const uint32_t b_off = (uint32_t)((((lane & 7) + ((lane >> 4) << 3)) * KP +
                                      (((lane >> 3) & 1) << 3)) * 2);

    auto load_stage = [&](int s, int kt) {
        __nv_bfloat16* As = smem + s * STAGE_ELEMS;
        __nv_bfloat16* Bs = As + ASZ;
        #pragma unroll
        for (int i = 0; i < 4; i++) {                // A: 1024 chunks
            int c   = tid + i * 256;
            int row = c >> 3;
            int kc  = (c & 7) * 8;
            cpa16(As + row * KP + kc,
                  g_Abf + (size_t)(bm * BM + row) * SMALLN + kt + kc);
        }
        #pragma unroll
        for (int i = 0; i < 8; i++) {                // B: 2048 chunks
            int c   = tid + i * 256;
            int row = c >> 3;
            int kc  = (c & 7) * 8;
            cpa16(Bs + row * KP + kc,
                  g_Bbf + (size_t)(bn * BN + row) * SMALLN + kt + kc);
        }
    };

    float acc[4][8][4];
    #pragma unroll
    for (int mi = 0; mi < 4; mi++)
        #pragma unroll
        for (int ni = 0; ni < 8; ni++)
            #pragma unroll
            for (int r = 0; r < 4; r++) acc[mi][ni][r] = 0.f;

    // ---- prologue: fill 2 stages (R9 order) ----
    load_stage(0, 0);
    asm volatile("cp.async.commit_group;\n");
    load_stage(1, BK);
    asm volatile("cp.async.commit_group;\n");

    // ---- one-time L2 prefetch of epilogue residual lines (outside loop) ----
    __syncthreads();                                  // sids visible
    #pragma unroll
    for (int i = 0; i < 8; i++) {
        int u = tid + i * 256;                        // 0..2047
        int row = u >> 4;                             // 0..127
        int ln  = u & 15;                             // 16 x 128B = 2KB/row
        prefetchL2(residual + (size_t)sids[row] * LARGEN + SMALLN + ln * 32);
    }

    // ---- mainloop: 8 K-tiles (byte-identical to R9) ----
    #pragma unroll 1
    for (int kt8 = 0; kt8 < 8; kt8++) {
        asm volatile("cp.async.wait_group 1;\n");
        __syncthreads();

        if (kt8 + 2 < 8) load_stage((kt8 + 2) % STAGES, (kt8 + 2) * BK);
        asm volatile("cp.async.commit_group;\n");

        const uint32_t As = smem_b + (uint32_t)((kt8 % STAGES) * STAGE_ELEMS) * 2;
        const uint32_t Bs = As + ASZ * 2;

        #pragma unroll
        for (int kh = 0; kh < 4; kh++) {
            const int kk = kh * 16;
            uint32_t af[4][4], bf[8][2];
            #pragma unroll
            for (int mi = 0; mi < 4; mi++) {
                int r0i = wm * 64 + mi * 16;
                ldsm_x4(af[mi][0], af[mi][1], af[mi][2], af[mi][3],
                        As + a_off + (uint32_t)((r0i * KP + kk) * 2));
            }
            #pragma unroll
            for (int nb = 0; nb < 4; nb++) {
                int n0 = wn * 64 + nb * 16;
                ldsm_x4(bf[nb * 2][0], bf[nb * 2][1],
                        bf[nb * 2 + 1][0], bf[nb * 2 + 1][1],
                        Bs + b_off + (uint32_t)((n0 * KP + kk) * 2));
            }
            #pragma unroll
            for (int mi = 0; mi < 4; mi++)
                #pragma unroll
                for (int ni = 0; ni < 8; ni++) {
                    asm volatile(
                        "mma.sync.aligned.m16n8k16.row.col.f32.bf16.bf16.f32 "
                        "{%0,%1,%2,%3}, {%4,%5,%6,%7}, {%8,%9}, {%0,%1,%2,%3};\n"
                        : "+f"(acc[mi][ni][0]), "+f"(acc[mi][ni][1]),
                          "+f"(acc[mi][ni][2]), "+f"(acc[mi][ni][3])
                        : "r"(af[mi][0]), "r"(af[mi][1]), "r"(af[mi][2]), "r"(af[mi][3]),
                          "r"(bf[ni][0]), "r"(bf[ni][1]));
                }
        }
    }

    // ---- epilogue: + residual[id, 512+col] -> out[t, 512+col] ----
    #pragma unroll
    for (int mi = 0; mi < 4; mi++) {
        const int lr0 = wm * 64 + mi * 16 + g;
        const int t0  = bm * BM + lr0;
        const int id0 = sids[lr0];
        const int id1 = sids[lr0 + 8];
        #pragma unroll
        for (int ni = 0; ni < 8; ni++) {
            const int col = bn * BN + wn * 64 + ni * 8 + tg * 2;   // 0..511
            {
                float2 rv = *reinterpret_cast<const float2*>(
                    residual + (size_t)id0 * LARGEN + SMALLN + col);
                float2 o;
                o.x = acc[mi][ni][0] + rv.x;
                o.y = acc[mi][ni][1] + rv.y;
                *reinterpret_cast<float2*>(
                    out + (size_t)t0 * LARGEN + SMALLN + col) = o;
            }
            {
                float2 rv = *reinterpret_cast<const float2*>(
                    residual + (size_t)id1 * LARGEN + SMALLN + col);
                float2 o;
                o.x = acc[mi][ni][2] + rv.x;
                o.y = acc[mi][ni][3] + rv.y;
                *reinterpret_cast<float2*>(
                    out + (size_t)(t0 + 8) * LARGEN + SMALLN + col) = o;
            }
        }
    }
}

// ---------------------------------------------------------------------------
// Launch
// ---------------------------------------------------------------------------
extern "C" void kernel_launch(void* const* d_in, const int* in_sizes, int n_in,
                              void* d_out, int out_size) {
    const int*   ids      = (const int*)  d_in[0];  // [4,2048]
    const float* weight   = (const float*)d_in[1];  // [50257,512]
    const float* cw       = (const float*)d_in[2];  // [512,512]
    const float* residual = (const float*)d_in[3];  // [50257,1024]
    float* out = (float*)d_out;                     // [8192,1024]

    cudaFuncSetAttribute(gemm_second_half,
                         cudaFuncAttributeMaxDynamicSharedMemorySize, SMEM_BYTES);

    // merged prep (2 units/thread): first half, Abf, Bbf
    prep_kernel<<<PREP_THREADS / 256, 256>>>(
        ids,
        reinterpret_cast<const float4*>(weight),
        reinterpret_cast<const float4*>(residual),
        reinterpret_cast<const float4*>(cw),
        reinterpret_cast<float4*>(out));

    // pipelined GEMM + residual epilogue (one wave: 128 CTAs)
    {
        dim3 grid(SMALLN / BN, NTOK / BM);          // (2, 64)
        gemm_second_half<<<grid, 256, SMEM_BYTES>>>(ids, residual, out);
    }
}

// round 17
// speedup vs baseline: 1.4568x; 1.4568x over previous
#include <cuda_runtime.h>
#include <cuda_bf16.h>
#include <cstdint>

// Problem constants
#define VOCABN 50257
#define SMALLN 512
#define LARGEN 1024
#define NTOK   8192      // B*S = 4*2048

// bf16 staging buffers (device globals: allocation-free scratch)
__device__ __nv_bfloat16 g_Abf[NTOK * SMALLN];    // gathered weight rows, bf16
__device__ __nv_bfloat16 g_Bbf[SMALLN * SMALLN];  // cw, bf16

// ---------------------------------------------------------------------------
// Kernel 1 (merged prep, MLP=4): one thread owns TWO column-pairs of the
// SAME token row -> one id load feeds 4 independent LDG.128.
//   gather threads [0, NTOK*64):  t = u>>6, cols c and c+64 (float4 units)
//   cw threads     [NTOK*64, +32768): float4 units i and i+32768
// ---------------------------------------------------------------------------
#define GATHER_THREADS (NTOK * 64)                 // 524,288
#define CW_THREADS     (SMALLN * SMALLN / 8)       // 32,768
#define PREP_THREADS   (GATHER_THREADS + CW_THREADS)  // 557,056

__global__ void prep_kernel(const int* __restrict__ ids,
                            const float4* __restrict__ w4,     // [VOCAB][128]
                            const float4* __restrict__ r4,     // [VOCAB][256]
                            const float4* __restrict__ cw4,    // [512][128]
                            float4* __restrict__ out4) {       // [NTOK][256]
    int u = blockIdx.x * blockDim.x + threadIdx.x;
    if (u < GATHER_THREADS) {
        int t = u >> 6;
        int c = u & 63;                 // columns c and c+64
        int id = ids[t];
        const float4* wrow = w4 + (size_t)id * 128;
        const float4* rrow = r4 + (size_t)id * 256;
        // 4 independent gathered loads
        float4 a0 = wrow[c];
        float4 a1 = wrow[c + 64];
        float4 b0 = rrow[c];
        float4 b1 = rrow[c + 64];
        // first-half out = w + r
        float4 o0, o1;
        o0.x = a0.x + b0.x; o0.y = a0.y + b0.y;
        o0.z = a0.z + b0.z; o0.w = a0.w + b0.w;
        o1.x = a1.x + b1.x; o1.y = a1.y + b1.y;
        o1.z = a1.z + b1.z; o1.w = a1.w + b1.w;
        out4[(size_t)t * 256 + c]      = o0;
        out4[(size_t)t * 256 + c + 64] = o1;
        // Abf staging (bf16)
        __nv_bfloat162* ap = reinterpret_cast<__nv_bfloat162*>(
            g_Abf + (size_t)t * SMALLN);
        __nv_bfloat162 p;
        p.x = __float2bfloat16(a0.x); p.y = __float2bfloat16(a0.y);
        ap[c * 2] = p;
        p.x = __float2bfloat16(a0.z); p.y = __float2bfloat16(a0.w);
        ap[c * 2 + 1] = p;
        p.x = __float2bfloat16(a1.x); p.y = __float2bfloat16(a1.y);
        ap[(c + 64) * 2] = p;
        p.x = __float2bfloat16(a1.z); p.y = __float2bfloat16(a1.w);
        ap[(c + 64) * 2 + 1] = p;
    } else {
        int i = u - GATHER_THREADS;     // 0..32767
        float4 v0 = cw4[i];
        float4 v1 = cw4[i + CW_THREADS];
        __nv_bfloat162* bp = reinterpret_cast<__nv_bfloat162*>(g_Bbf);
        __nv_bfloat162 p;
        p.x = __float2bfloat16(v0.x); p.y = __float2bfloat16(v0.y);
        bp[i * 2] = p;
        p.x = __float2bfloat16(v0.z); p.y = __float2bfloat16(v0.w);
        bp[i * 2 + 1] = p;
        p.x = __float2bfloat16(v1.x); p.y = __float2bfloat16(v1.y);
        bp[(i + CW_THREADS) * 2] = p;
        p.x = __float2bfloat16(v1.z); p.y = __float2bfloat16(v1.w);
        bp[(i + CW_THREADS) * 2 + 1] = p;
    }
}

// ---------------------------------------------------------------------------
// Kernel 2: EXACT R9 GEMM — byte-identical source, DO NOT TOUCH.
// BM=128, BN=256, BK=64, 256 threads (8 warps 2x4), warp tile 64x64.
// Grid (2, 64) = 128 CTAs = one wave. Measured 24.48 us.
// ---------------------------------------------------------------------------
#define BM 128
#define BN 256
#define BK 64
#define KP 72
#define STAGES 3
#define ASZ (BM * KP)
#define BSZ (BN * KP)
#define STAGE_ELEMS (ASZ + BSZ)
#define SMEM_BYTES (STAGES * STAGE_ELEMS * 2)   // 165,888 B

__device__ __forceinline__ void cpa16(void* sm, const void* g) {
    uint32_t s = (uint32_t)__cvta_generic_to_shared(sm);
    asm volatile("cp.async.cg.shared.global [%0], [%1], 16;\n" :: "r"(s), "l"(g));
}
__device__ __forceinline__ void ldsm_x4(uint32_t& d0, uint32_t& d1,
                                        uint32_t& d2, uint32_t& d3, uint32_t a) {
    asm volatile("ldmatrix.sync.aligned.m8n8.x4.shared.b16 {%0,%1,%2,%3}, [%4];"
                 : "=r"(d0), "=r"(d1), "=r"(d2), "=r"(d3) : "r"(a));
}

__global__ __launch_bounds__(256, 1)
void gemm_second_half(const int* __restrict__ ids,
                      const float* __restrict__ residual,   // [VOCAB][1024]
                      float* __restrict__ out) {            // [NTOK][1024]
    extern __shared__ __nv_bfloat16 smem[];
    __shared__ int sids[BM];

    const int bn = blockIdx.x;        // 0..1
    const int bm = blockIdx.y;        // 0..63
    const int tid  = threadIdx.x;
    const int warp = tid >> 5;
    const int lane = tid & 31;
    const int wm = warp >> 2;         // 0..1  (64-row slab)
    const int wn = warp & 3;          // 0..3  (64-col slab)
    const int g  = lane >> 2;         // 0..7
    const int tg = lane & 3;          // 0..3

    if (tid < BM) sids[tid] = ids[bm * BM + tid];

    const uint32_t smem_b = (uint32_t)__cvta_generic_to_shared(smem);
    const uint32_t a_off = (uint32_t)(((lane & 15) * KP + ((lane >> 4) << 3)) * 2);
    const uint32_t b_off = (uint32_t)((((lane & 7) + ((lane >> 4) << 3)) * KP +
                                      (((lane >> 3) & 1) << 3)) * 2);

    auto load_stage = [&](int s, int kt) {
        __nv_bfloat16* As = smem + s * STAGE_ELEMS;
        __nv_bfloat16* Bs = As + ASZ;
        #pragma unroll
        for (int i = 0; i < 4; i++) {                // A: 1024 chunks
            int c   = tid + i * 256;
            int row = c >> 3;
            int kc  = (c & 7) * 8;
            cpa16(As + row * KP + kc,
                  g_Abf + (size_t)(bm * BM + row) * SMALLN + kt + kc);
        }
        #pragma unroll
        for (int i = 0; i < 8; i++) {                // B: 2048 chunks
            int c   = tid + i * 256;
            int row = c >> 3;
            int kc  = (c & 7) * 8;
            cpa16(Bs + row * KP + kc,
                  g_Bbf + (size_t)(bn * BN + row) * SMALLN + kt + kc);
        }
    };

    float acc[4][8][4];
    #pragma unroll
    for (int mi = 0; mi < 4; mi++)
        #pragma unroll
        for (int ni = 0; ni < 8; ni++)
            #pragma unroll
            for (int r = 0; r < 4; r++) acc[mi][ni][r] = 0.f;

    // ---- prologue: fill 2 stages ----
    load_stage(0, 0);
    asm volatile("cp.async.commit_group;\n");
    load_stage(1, BK);
    asm volatile("cp.async.commit_group;\n");

    // ---- mainloop: 8 K-tiles ----
    #pragma unroll 1
    for (int kt8 = 0; kt8 < 8; kt8++) {
        asm volatile("cp.async.wait_group 1;\n");
        __syncthreads();

        if (kt8 + 2 < 8) load_stage((kt8 + 2) % STAGES, (kt8 + 2) * BK);
        asm volatile("cp.async.commit_group;\n");

        const uint32_t As = smem_b + (uint32_t)((kt8 % STAGES) * STAGE_ELEMS) * 2;
        const uint32_t Bs = As + ASZ * 2;

        #pragma unroll
        for (int kh = 0; kh < 4; kh++) {
            const int kk = kh * 16;
            uint32_t af[4][4], bf[8][2];
            #pragma unroll
            for (int mi = 0; mi < 4; mi++) {
                int r0i = wm * 64 + mi * 16;
                ldsm_x4(af[mi][0], af[mi][1], af[mi][2], af[mi][3],
                        As + a_off + (uint32_t)((r0i * KP + kk) * 2));
            }
            #pragma unroll
            for (int nb = 0; nb < 4; nb++) {
                int n0 = wn * 64 + nb * 16;
                ldsm_x4(bf[nb * 2][0], bf[nb * 2][1],
                        bf[nb * 2 + 1][0], bf[nb * 2 + 1][1],
                        Bs + b_off + (uint32_t)((n0 * KP + kk) * 2));
            }
            #pragma unroll
            for (int mi = 0; mi < 4; mi++)
                #pragma unroll
                for (int ni = 0; ni < 8; ni++) {
                    asm volatile(
                        "mma.sync.aligned.m16n8k16.row.col.f32.bf16.bf16.f32 "
                        "{%0,%1,%2,%3}, {%4,%5,%6,%7}, {%8,%9}, {%0,%1,%2,%3};\n"
                        : "+f"(acc[mi][ni][0]), "+f"(acc[mi][ni][1]),
                          "+f"(acc[mi][ni][2]), "+f"(acc[mi][ni][3])
                        : "r"(af[mi][0]), "r"(af[mi][1]), "r"(af[mi][2]), "r"(af[mi][3]),
                          "r"(bf[ni][0]), "r"(bf[ni][1]));
                }
        }
    }

    // ---- epilogue: + residual[id, 512+col] -> out[t, 512+col] ----
    #pragma unroll
    for (int mi = 0; mi < 4; mi++) {
        const int lr0 = wm * 64 + mi * 16 + g;
        const int t0  = bm * BM + lr0;
        const int id0 = sids[lr0];
        const int id1 = sids[lr0 + 8];
        #pragma unroll
        for (int ni = 0; ni < 8; ni++) {
            const int col = bn * BN + wn * 64 + ni * 8 + tg * 2;   // 0..511
            {
                float2 rv = *reinterpret_cast<const float2*>(
                    residual + (size_t)id0 * LARGEN + SMALLN + col);
                float2 o;
                o.x = acc[mi][ni][0] + rv.x;
                o.y = acc[mi][ni][1] + rv.y;
                *reinterpret_cast<float2*>(
                    out + (size_t)t0 * LARGEN + SMALLN + col) = o;
            }
            {
                float2 rv = *reinterpret_cast<const float2*>(
                    residual + (size_t)id1 * LARGEN + SMALLN + col);
                float2 o;
                o.x = acc[mi][ni][2] + rv.x;
                o.y = acc[mi][ni][3] + rv.y;
                *reinterpret_cast<float2*>(
                    out + (size_t)(t0 + 8) * LARGEN + SMALLN + col) = o;
            }
        }
    }
}

// ---------------------------------------------------------------------------
// Launch
// ---------------------------------------------------------------------------
extern "C" void kernel_launch(void* const* d_in, const int* in_sizes, int n_in,
                              void* d_out, int out_size) {
    const int*   ids      = (const int*)  d_in[0];  // [4,2048]
    const float* weight   = (const float*)d_in[1];  // [50257,512]
    const float* cw       = (const float*)d_in[2];  // [512,512]
    const float* residual = (const float*)d_in[3];  // [50257,1024]
    float* out = (float*)d_out;                     // [8192,1024]

    cudaFuncSetAttribute(gemm_second_half,
                         cudaFuncAttributeMaxDynamicSharedMemorySize, SMEM_BYTES);

    // merged prep (MLP=4 per thread): first half, Abf, Bbf
    prep_kernel<<<PREP_THREADS / 256, 256>>>(
        ids,
        reinterpret_cast<const float4*>(weight),
        reinterpret_cast<const float4*>(residual),
        reinterpret_cast<const float4*>(cw),
        reinterpret_cast<float4*>(out));

    // pipelined GEMM + residual epilogue (one wave: 128 CTAs)
    {
        dim3 grid(SMALLN / BN, NTOK / BM);          // (2, 64)
        gemm_second_half<<<grid, 256, SMEM_BYTES>>>(ids, residual, out);
    }
}